// round 6
// baseline (speedup 1.0000x reference)
#include <cuda_runtime.h>
#include <cstdint>
#include <cstddef>

// ============================================================================
// VQ quantizer: legacy mma.sync m16n8k32 s8, 2-digit base-128 fixed point,
// 3-pass (hh<<7 + hl + lh) exact int32 accumulation
// + per-row margin check with batched exact-fp32 fallback
//   grid_feat [8,256,16,16,16] f32 ; weight [4096,256] f32
// out: quant_feat[8.4M] | quant_feat_st[8.4M] | enc_idx[32768] | quant_diff[1]
// ============================================================================

namespace {
constexpr int KDIM    = 256;
constexpr int VCODES  = 4096;
constexpr int SPATIAL = 4096;
constexpr int NROWS   = 32768;
constexpr long long NQ = 8388608LL;

constexpr int MT  = 128;            // rows per CTA
constexpr int NTT = 256;            // codes per v-tile
constexpr int NRT = NROWS / MT;     // 256 row-tile CTAs
constexpr int NVT = VCODES / NTT;   // 16 v-tiles
constexpr int NCH = 8;              // k-chunks per pass (256/32)

// chunk = 32 k ; per vt: 3 passes x 8 chunks
constexpr int CH_PER_VT = 24;
constexpr int TOTAL_CH  = NVT * CH_PER_VT;      // 384
constexpr int A_CH_F4   = 256;                  // 8 mt x 32 lanes (4KB)
constexpr int B_CH_F4   = 512;                  // 16 ntp x 32 lanes (8KB)
constexpr int STAGE_F4  = A_CH_F4 + B_CH_F4;    // 768 f4 (12KB)
constexpr int NSTAGES   = 6;
constexpr int SMEM_MAIN = NSTAGES * STAGE_F4 * 16;   // 73728 B

// fixed-point: q = round(f * 2032), |q| <= 16256 (covers +-8.0)
constexpr float INV_DELTA = 2032.0f;
constexpr float SCALE2 = 2.0f * 128.0f / (2032.0f * 2032.0f);  // 2*128*Delta^2
constexpr float MARGIN = 0.1f;      // ~8 sigma of 3-pass int8 distance error
constexpr int   FLAGCAP = 32768;
}

// --------------------------- device scratch --------------------------------
__device__ uint32_t g_A8[(size_t)NRT * 2 * NCH * A_CH_F4 * 4];  // 16 MB
__device__ uint32_t g_B8[(size_t)NVT * 2 * NCH * B_CH_F4 * 4];  // 2 MB
__device__ float    g_Wt[KDIM * VCODES];                        // W^T gather
__device__ float    g_wnorm[VCODES];
__device__ float    g_partial[NRT];
__device__ int      g_nflag;
__device__ int      g_flagrows[FLAGCAP];

// --------------------------- helpers ---------------------------------------
__device__ __forceinline__ uint32_t smem_u32(const void* p) {
    uint32_t a;
    asm("{ .reg .u64 t; cvta.to.shared.u64 t, %1; cvt.u32.u64 %0, t; }"
        : "=r"(a) : "l"(p));
    return a;
}
__device__ __forceinline__ void cp16(uint32_t s, const void* g) {
    asm volatile("cp.async.cg.shared.global [%0], [%1], 16;" :: "r"(s), "l"(g));
}
#define CP_COMMIT()  asm volatile("cp.async.commit_group;" ::: "memory")
#define CP_WAIT(N)   asm volatile("cp.async.wait_group %0;" :: "n"(N) : "memory")

__device__ __forceinline__ void imma16832(int* c, const uint4& a,
                                          uint32_t b0, uint32_t b1) {
    asm volatile(
        "mma.sync.aligned.m16n8k32.row.col.s32.s8.s8.s32 "
        "{%0,%1,%2,%3}, {%4,%5,%6,%7}, {%8,%9}, {%0,%1,%2,%3};"
        : "+r"(c[0]), "+r"(c[1]), "+r"(c[2]), "+r"(c[3])
        : "r"(a.x), "r"(a.y), "r"(a.z), "r"(a.w), "r"(b0), "r"(b1));
}

// q = d0*128 + d1, d0 in [-127,127], d1 in [-64,63]
__device__ __forceinline__ void qsplit(float v, int& d0, int& d1) {
    int q = __float2int_rn(v * INV_DELTA);
    q = max(-16256, min(16256, q));
    d0 = (q + 64) >> 7;
    d1 = q - (d0 << 7);
}
__device__ __forceinline__ uint32_t pack4(int b0, int b1, int b2, int b3) {
    return (uint32_t)(b0 & 0xFF) | ((uint32_t)(b1 & 0xFF) << 8)
         | ((uint32_t)(b2 & 0xFF) << 16) | ((uint32_t)(b3 & 0xFF) << 24);
}

// ============================================================================
// Prep A: grid_feat -> fragment-major s8 digit images
// block = (rt 256, ch 8); ch covers channels [ch*32, ch*32+32)
// image layout: g_A8 as uint4[(rt*2 + digit)*8 + ch][256]
// ============================================================================
__global__ void vq_prepA(const float* __restrict__ gf) {
    __shared__ float sr[32 * 129];
    const int rt = blockIdx.x, ch = blockIdx.y, t = threadIdx.x;
    const int n0 = rt * MT, b = n0 >> 12, p0 = n0 & (SPATIAL - 1);
    const float* base = gf + (size_t)b * KDIM * SPATIAL + (size_t)(ch * 32) * SPATIAL + p0;

    for (int i = t; i < 32 * 128; i += 256) {
        const int c = i >> 7, r = i & 127;          // coalesced along spatial
        sr[c * 129 + r] = base[(size_t)c * SPATIAL + r];
    }
    __syncthreads();

    // one (mt, lane) tuple per thread: 8 mt x 32 lanes = 256
    const int mt = t >> 5, l = t & 31;
    const int row0 = mt * 16 + (l >> 2);
    const int k0 = (l & 3) * 4;
    uint32_t hi[4], lo[4];
    #pragma unroll
    for (int rsel = 0; rsel < 4; rsel++) {
        const int kk = k0 + ((rsel & 2) ? 16 : 0);   // regs 0,1: k0 ; 2,3: k0+16
        const int rr = row0 + ((rsel & 1) ? 8 : 0);
        int h[4], d[4];
        #pragma unroll
        for (int j = 0; j < 4; j++) qsplit(sr[(kk + j) * 129 + rr], h[j], d[j]);
        hi[rsel] = pack4(h[0], h[1], h[2], h[3]);
        lo[rsel] = pack4(d[0], d[1], d[2], d[3]);
    }
    uint4* obH = (uint4*)g_A8 + (size_t)((rt * 2 + 0) * NCH + ch) * A_CH_F4;
    uint4* obL = (uint4*)g_A8 + (size_t)((rt * 2 + 1) * NCH + ch) * A_CH_F4;
    obH[mt * 32 + l] = make_uint4(hi[0], hi[1], hi[2], hi[3]);
    obL[mt * 32 + l] = make_uint4(lo[0], lo[1], lo[2], lo[3]);
}

// ============================================================================
// Prep B: weight -> fragment-major s8 digit images. block = (vt 16, ch 8)
// uint4 = {tile0.b0, tile0.b1, tile1.b0, tile1.b1} per 16-col pair
// ============================================================================
__global__ void vq_prepB(const float* __restrict__ W) {
    __shared__ float sr2[32 * 257];
    const int vt = blockIdx.x, ch = blockIdx.y, t = threadIdx.x;
    const float* base = W + (size_t)(vt * NTT) * KDIM + ch * 32;

    for (int i = t; i < 256 * 32; i += 256) {
        const int n = i >> 5, c = i & 31;           // coalesced along channels
        sr2[c * 257 + n] = base[(size_t)n * KDIM + c];
    }
    __syncthreads();

    uint4* obH = (uint4*)g_B8 + (size_t)((vt * 2 + 0) * NCH + ch) * B_CH_F4;
    uint4* obL = (uint4*)g_B8 + (size_t)((vt * 2 + 1) * NCH + ch) * B_CH_F4;
    #pragma unroll
    for (int q = 0; q < 2; q++) {
        const int tup = q * 256 + t;                // 512 tuples: 16 ntp x 32 l
        const int ntp = tup >> 5, l = tup & 31;
        const int k0 = (l & 3) * 4;
        uint32_t hi[4], lo[4];
        #pragma unroll
        for (int rsel = 0; rsel < 4; rsel++) {
            const int col = ntp * 16 + (l >> 2) + ((rsel & 2) ? 8 : 0);
            const int kk = k0 + ((rsel & 1) ? 16 : 0);
            int h[4], d[4];
            #pragma unroll
            for (int j = 0; j < 4; j++) qsplit(sr2[(kk + j) * 257 + col], h[j], d[j]);
            hi[rsel] = pack4(h[0], h[1], h[2], h[3]);
            lo[rsel] = pack4(d[0], d[1], d[2], d[3]);
        }
        obH[ntp * 32 + l] = make_uint4(hi[0], hi[1], hi[2], hi[3]);
        obL[ntp * 32 + l] = make_uint4(lo[0], lo[1], lo[2], lo[3]);
    }
}

// ---- W transpose + ||w||^2 (validated R1) ; resets flag counter ------------
__global__ void vq_transpose(const float* __restrict__ W) {
    __shared__ float tile[32][33];
    const int v0 = blockIdx.x * 32, c0 = blockIdx.y * 32;
    const int tx = threadIdx.x, ty = threadIdx.y;
    #pragma unroll
    for (int j = 0; j < 32; j += 8)
        tile[ty + j][tx] = W[(size_t)(v0 + ty + j) * KDIM + c0 + tx];
    __syncthreads();
    #pragma unroll
    for (int j = 0; j < 32; j += 8)
        g_Wt[(size_t)(c0 + ty + j) * VCODES + v0 + tx] = tile[tx][ty + j];
}

__global__ void vq_wnorm(const float* __restrict__ W) {
    if (blockIdx.x == 0 && threadIdx.x == 0) g_nflag = 0;
    const int v = blockIdx.x * 8 + (threadIdx.x >> 5);
    const int lane = threadIdx.x & 31;
    const float4* p = reinterpret_cast<const float4*>(W + (size_t)v * KDIM);
    float s = 0.f;
    #pragma unroll
    for (int i = 0; i < 2; i++) {
        float4 x = p[lane * 2 + i];
        s += x.x * x.x + x.y * x.y + x.z * x.z + x.w * x.w;
    }
    #pragma unroll
    for (int o = 16; o > 0; o >>= 1) s += __shfl_xor_sync(0xffffffffu, s, o);
    if (lane == 0) g_wnorm[v] = s;
}

// ============================================================================
// Main: 256 CTAs x 256 threads, 6-stage cp.async pipeline, warp tile 32x128
// per v-tile: 8 hh chunks, acc <<= 7, then 8 hl + 8 lh chunks (exact int32)
// ============================================================================
__global__ void __launch_bounds__(256, 1)
vq_main(const float* __restrict__ gf, float* __restrict__ out) {
    extern __shared__ uint4 sm4[];
    const uint32_t smb = smem_u32(sm4);

    const int t  = threadIdx.x;
    const int l  = t & 31;
    const int w  = t >> 5;
    const int wr = w >> 1;       // 0..3 row group
    const int wc = w & 1;        // 0..1 col group
    const int rt = blockIdx.x;
    const int n0 = rt * MT;
    const int b  = n0 >> 12;
    const int p0 = n0 & (SPATIAL - 1);

    // pass 0: AhBh ; pass 1: AhBl ; pass 2: AlBh
    auto issue = [&](int ch, int slot) {
        const int vt = ch / CH_PER_VT, cc = ch - vt * CH_PER_VT;
        const int pass = cc >> 3, kc = cc & 7;
        const uint4* As = (const uint4*)g_A8
            + (size_t)((rt * 2 + (pass == 2 ? 1 : 0)) * NCH + kc) * A_CH_F4;
        const uint4* Bs = (const uint4*)g_B8
            + (size_t)((vt * 2 + (pass == 1 ? 1 : 0)) * NCH + kc) * B_CH_F4;
        const uint32_t sb = smb + slot * STAGE_F4 * 16;
        cp16(sb + t * 16,             As + t);
        cp16(sb + (256 + t) * 16,     Bs + t);
        cp16(sb + (512 + t) * 16,     Bs + t + 256);
        CP_COMMIT();
    };

    int   acc[2][16][4];
    float rmin[4], rmin2[4];
    int   ridx[4];
    #pragma unroll
    for (int q = 0; q < 4; q++) { rmin[q] = 3.4e38f; rmin2[q] = 3.4e38f; ridx[q] = 0; }

    issue(0, 0); issue(1, 1); issue(2, 2); issue(3, 3); issue(4, 4);

    for (int ch = 0; ch < TOTAL_CH; ch++) {
        if (ch + 5 < TOTAL_CH) {
            CP_WAIT(4);                 // group ch complete
            __syncthreads();            // all warps done reading slot (ch+5)%6
            issue(ch + 5, (ch + 5) % NSTAGES);
        } else {
            CP_WAIT(0);
            __syncthreads();
        }

        const uint4* S = sm4 + (ch % NSTAGES) * STAGE_F4;
        const int vt = ch / CH_PER_VT, cc = ch - vt * CH_PER_VT;

        if (cc == 0) {
            #pragma unroll
            for (int i = 0; i < 2; i++)
                #pragma unroll
                for (int j = 0; j < 16; j++)
                    #pragma unroll
                    for (int e = 0; e < 4; e++) acc[i][j][e] = 0;
        }
        if (cc == 8) {                  // fold: S = 128*S_hh, then += hl+lh
            #pragma unroll
            for (int i = 0; i < 2; i++)
                #pragma unroll
                for (int j = 0; j < 16; j++)
                    #pragma unroll
                    for (int e = 0; e < 4; e++) acc[i][j][e] <<= 7;
        }

        const uint4 a0 = S[(wr * 2 + 0) * 32 + l];
        const uint4 a1 = S[(wr * 2 + 1) * 32 + l];
        #pragma unroll
        for (int jp = 0; jp < 8; jp++) {
            const uint4 bb = S[A_CH_F4 + ((wc * 8 + jp) * 32 + l)];
            imma16832(acc[0][2 * jp],     a0, bb.x, bb.y);
            imma16832(acc[1][2 * jp],     a1, bb.x, bb.y);
            imma16832(acc[0][2 * jp + 1], a0, bb.z, bb.w);
            imma16832(acc[1][2 * jp + 1], a1, bb.z, bb.w);
        }

        if (cc == CH_PER_VT - 1) {
            // epilogue: d = ||w||^2 - SCALE2*S ; (min1,idx1) lex + min2
            #pragma unroll
            for (int i = 0; i < 2; i++) {
                #pragma unroll
                for (int jn = 0; jn < 16; jn++) {
                    const int cb = vt * NTT + (wc * 8 + (jn >> 1)) * 16
                                 + (jn & 1) * 8 + 2 * (l & 3);
                    const float w0 = __ldg(&g_wnorm[cb]);
                    const float w1 = __ldg(&g_wnorm[cb + 1]);
                    const float d0 = fmaf(-SCALE2, (float)acc[i][jn][0], w0);
                    const float d1 = fmaf(-SCALE2, (float)acc[i][jn][1], w1);
                    const float d2 = fmaf(-SCALE2, (float)acc[i][jn][2], w0);
                    const float d3 = fmaf(-SCALE2, (float)acc[i][jn][3], w1);
                    const int q0 = i * 2, q1 = i * 2 + 1;
                    if (d0 < rmin[q0]) { rmin2[q0] = rmin[q0]; rmin[q0] = d0; ridx[q0] = cb; }
                    else if (d0 < rmin2[q0]) rmin2[q0] = d0;
                    if (d1 < rmin[q0]) { rmin2[q0] = rmin[q0]; rmin[q0] = d1; ridx[q0] = cb + 1; }
                    else if (d1 < rmin2[q0]) rmin2[q0] = d1;
                    if (d2 < rmin[q1]) { rmin2[q1] = rmin[q1]; rmin[q1] = d2; ridx[q1] = cb; }
                    else if (d2 < rmin2[q1]) rmin2[q1] = d2;
                    if (d3 < rmin[q1]) { rmin2[q1] = rmin[q1]; rmin[q1] = d3; ridx[q1] = cb + 1; }
                    else if (d3 < rmin2[q1]) rmin2[q1] = d3;
                }
            }
        }
    }
    CP_WAIT(0);
    __syncthreads();

    // ---- cross-warp argmin merge (smem aliases pipeline stages) ------------
    float* dmin_s   = (float*)sm4;              // [128][8]
    int*   idx_s    = (int*)(dmin_s + 1024);    // [128][8]
    float* dmin2_s  = (float*)(idx_s + 1024);   // [128][8]
    int*   rowidx_s = (int*)(dmin2_s + 1024);   // [128]
    float* red      = (float*)(rowidx_s + 128); // [256]

    const int slot = wc * 4 + (l & 3);
    #pragma unroll
    for (int q = 0; q < 4; q++) {
        const int row = wr * 32 + (q >> 1) * 16 + (q & 1) * 8 + (l >> 2);
        dmin_s[row * 8 + slot]  = rmin[q];
        idx_s[row * 8 + slot]   = ridx[q];
        dmin2_s[row * 8 + slot] = rmin2[q];
    }
    __syncthreads();
    if (t < MT) {
        float bd = 3.4e38f, bd2 = 3.4e38f;
        int   bi = 0;
        #pragma unroll
        for (int s = 0; s < 8; s++) {
            const float d = dmin_s[t * 8 + s];
            const int   v = idx_s[t * 8 + s];
            if (d < bd || (d == bd && v < bi)) { bd2 = fminf(bd2, bd); bd = d; bi = v; }
            else bd2 = fminf(bd2, d);
            bd2 = fminf(bd2, dmin2_s[t * 8 + s]);
        }
        rowidx_s[t] = bi;
        out[2 * NQ + n0 + t] = (float)bi;       // enc_idx
        if (bd2 - bd < MARGIN) {                // ambiguous -> exact fallback
            const int pos = atomicAdd(&g_nflag, 1);
            if (pos < FLAGCAP) g_flagrows[pos] = n0 + t;
        }
    }
    __syncthreads();

    // ---- output phase: gather + straight-through + MSE partial -------------
    float diffsum = 0.f;
    const size_t obase = (size_t)b * KDIM * SPATIAL + p0;
    for (int i = t; i < MT * KDIM; i += 256) {
        const int c = i >> 7, r = i & 127;
        const int vi = rowidx_s[r];
        const float qv = g_Wt[(size_t)c * VCODES + vi];
        const float gv = gf[obase + (size_t)c * SPATIAL + r];
        const float st = (qv - gv) + gv;
        const float dd = gv - qv;
        diffsum += dd * dd;
        const size_t o = obase + (size_t)c * SPATIAL + r;
        out[o]      = qv;
        out[NQ + o] = st;
    }

    red[t] = diffsum;
    __syncthreads();
    #pragma unroll
    for (int o = 128; o > 0; o >>= 1) {
        if (t < o) red[t] += red[t + o];
        __syncthreads();
    }
    if (t == 0) g_partial[rt] = red[0];
}

// ============================================================================
// Exact fp32 fallback, batched 16 flagged rows per block (W^T read once/group)
// ============================================================================
__global__ void vq_fix(const float* __restrict__ gf, float* __restrict__ out) {
    const int nf = min(g_nflag, FLAGCAP);
    __shared__ float fsh[16][KDIM];
    __shared__ float dsh[256];
    __shared__ int   ish[256];
    __shared__ int   rowid_s[16];
    const int t = threadIdx.x;

    for (int g = blockIdx.x; g * 16 < nf; g += gridDim.x) {
        const int ng = min(16, nf - g * 16);
        if (t < ng) rowid_s[t] = g_flagrows[g * 16 + t];
        __syncthreads();
        for (int rw = 0; rw < ng; rw++) {
            const int row = rowid_s[rw];
            const int b = row >> 12, p = row & (SPATIAL - 1);
            fsh[rw][t] = gf[(size_t)b * KDIM * SPATIAL + (size_t)t * SPATIAL + p];
        }
        __syncthreads();

        float bd[16]; int bi[16];
        #pragma unroll
        for (int rw = 0; rw < 16; rw++) { bd[rw] = 3.4e38f; bi[rw] = 0; }

        for (int v = t; v < VCODES; v += 256) {     // coalesced over g_Wt [c][v]
            float dot[16];
            #pragma unroll
            for (int rw = 0; rw < 16; rw++) dot[rw] = 0.f;
            for (int c = 0; c < KDIM; c++) {
                const float wv = g_Wt[(size_t)c * VCODES + v];
                #pragma unroll
                for (int rw = 0; rw < 16; rw++)
                    dot[rw] = fmaf(fsh[rw][c], wv, dot[rw]);
            }
            const float wn = g_wnorm[v];
            #pragma unroll
            for (int rw = 0; rw < 16; rw++) {
                const float d = fmaf(-2.f, dot[rw], wn);
                if (d < bd[rw]) { bd[rw] = d; bi[rw] = v; }  // ascending v
            }
        }

        for (int rw = 0; rw < ng; rw++) {
            dsh[t] = bd[rw]; ish[t] = bi[rw];
            __syncthreads();
            #pragma unroll
            for (int o = 128; o > 0; o >>= 1) {
                if (t < o) {
                    const float d2 = dsh[t + o]; const int i2 = ish[t + o];
                    if (d2 < dsh[t] || (d2 == dsh[t] && i2 < ish[t])) {
                        dsh[t] = d2; ish[t] = i2;
                    }
                }
                __syncthreads();
            }
            const int row = rowid_s[rw];
            const int newi = ish[0];
            const int oldi = (int)out[2 * NQ + row];
            __syncthreads();
            if (newi != oldi) {
                const int b = row >> 12, p = row & (SPATIAL - 1);
                const float gv = fsh[rw][t];
                const float qn = g_Wt[(size_t)t * VCODES + newi];
                const float qo = g_Wt[(size_t)t * VCODES + oldi];
                const size_t o = (size_t)b * KDIM * SPATIAL + (size_t)t * SPATIAL + p;
                out[o]      = qn;
                out[NQ + o] = (qn - gv) + gv;
                dsh[t] = (gv - qn) * (gv - qn) - (gv - qo) * (gv - qo);
                __syncthreads();
                #pragma unroll
                for (int o2 = 128; o2 > 0; o2 >>= 1) {
                    if (t < o2) dsh[t] += dsh[t + o2];
                    __syncthreads();
                }
                if (t == 0) {
                    atomicAdd(&g_partial[row / MT], dsh[0]);
                    out[2 * NQ + row] = (float)newi;
                }
            }
            __syncthreads();
        }
    }
}

__global__ void vq_final(float* __restrict__ out) {
    __shared__ float red[NRT];
    const int t = threadIdx.x;
    red[t] = g_partial[t];
    __syncthreads();
    #pragma unroll
    for (int o = 128; o > 0; o >>= 1) {
        if (t < o) red[t] += red[t + o];
        __syncthreads();
    }
    if (t == 0) out[2 * NQ + NROWS] = red[0] * (1.f / (float)NQ);
}

// ============================================================================
extern "C" void kernel_launch(void* const* d_in, const int* in_sizes, int n_in,
                              void* d_out, int out_size) {
    const float* grid_feat = (const float*)d_in[0];
    const float* weight    = (const float*)d_in[1];
    float* out = (float*)d_out;

    cudaFuncSetAttribute(vq_main,
                         cudaFuncAttributeMaxDynamicSharedMemorySize, SMEM_MAIN);

    vq_prepA<<<dim3(NRT, NCH), 256>>>(grid_feat);
    vq_prepB<<<dim3(NVT, NCH), 256>>>(weight);
    vq_transpose<<<dim3(VCODES / 32, KDIM / 32), dim3(32, 8)>>>(weight);
    vq_wnorm<<<VCODES / 8, 256>>>(weight);
    vq_main<<<NRT, 256, SMEM_MAIN>>>(grid_feat, out);
    vq_fix<<<128, 256>>>(grid_feat, out);
    vq_final<<<1, NRT>>>(out);
}

// round 7
// speedup vs baseline: 1.2394x; 1.2394x over previous
#include <cuda_runtime.h>
#include <cuda_fp16.h>
#include <cstdint>
#include <cstddef>

// ============================================================================
// VQ quantizer: legacy mma.sync m16n8k16 fp16 SINGLE pass (hi*hi)
// + per-row margin check (0.2) + batched exact-fp32 fallback for flagged rows
//   grid_feat [8,256,16,16,16] f32 ; weight [4096,256] f32
// out: quant_feat[8.4M] | quant_feat_st[8.4M] | enc_idx[32768] | quant_diff[1]
// ============================================================================

namespace {
constexpr int KDIM    = 256;
constexpr int VCODES  = 4096;
constexpr int SPATIAL = 4096;
constexpr int NROWS   = 32768;
constexpr long long NQ = 8388608LL;

constexpr int MT  = 128;            // rows per CTA
constexpr int NTT = 256;            // codes per v-tile
constexpr int NRT = NROWS / MT;     // 256 row-tile CTAs
constexpr int NVT = VCODES / NTT;   // 16 v-tiles
constexpr int NCH = 8;              // k-chunks (256/32)

constexpr int CH_PER_VT = 8;        // single pass
constexpr int TOTAL_CH  = NVT * CH_PER_VT;      // 128
constexpr int A_CH_F4   = 512;                  // 2 kt x 8 mt x 32 l (8KB)
constexpr int B_CH_F4   = 1024;                 // 2 kt x 16 ntp x 32 l (16KB)
constexpr int STAGE_F4  = A_CH_F4 + B_CH_F4;    // 1536 f4 (24KB)
constexpr int NSTAGES   = 4;
constexpr int SMEM_MAIN = NSTAGES * STAGE_F4 * 16;   // 98304 B

constexpr float MARGIN = 0.2f;      // ~2x worst-case 1-pass distance error
constexpr int   FLAGCAP = 32768;
}

// --------------------------- device scratch --------------------------------
__device__ uint32_t g_Aimg[(size_t)NRT * NCH * A_CH_F4 * 4];  // 16 MB (hi only)
__device__ uint32_t g_Bimg[(size_t)NVT * NCH * B_CH_F4 * 4];  // 2 MB  (hi only)
__device__ float    g_Wt[KDIM * VCODES];                      // W^T gather
__device__ float    g_wnorm[VCODES];
__device__ float    g_partial[NRT];
__device__ int      g_nflag;
__device__ int      g_flagrows[FLAGCAP];

// --------------------------- helpers ---------------------------------------
__device__ __forceinline__ uint32_t smem_u32(const void* p) {
    uint32_t a;
    asm("{ .reg .u64 t; cvta.to.shared.u64 t, %1; cvt.u32.u64 %0, t; }"
        : "=r"(a) : "l"(p));
    return a;
}
__device__ __forceinline__ void cp16(uint32_t s, const void* g) {
    asm volatile("cp.async.cg.shared.global [%0], [%1], 16;" :: "r"(s), "l"(g));
}
#define CP_COMMIT()  asm volatile("cp.async.commit_group;" ::: "memory")
#define CP_WAIT(N)   asm volatile("cp.async.wait_group %0;" :: "n"(N) : "memory")

__device__ __forceinline__ void mma16816(float* c, const uint4& a,
                                         uint32_t b0, uint32_t b1) {
    asm volatile(
        "mma.sync.aligned.m16n8k16.row.col.f32.f16.f16.f32 "
        "{%0,%1,%2,%3}, {%4,%5,%6,%7}, {%8,%9}, {%0,%1,%2,%3};"
        : "+f"(c[0]), "+f"(c[1]), "+f"(c[2]), "+f"(c[3])
        : "r"(a.x), "r"(a.y), "r"(a.z), "r"(a.w), "r"(b0), "r"(b1));
}

__device__ __forceinline__ uint32_t pack2h(float v0, float v1) {
    __half h0 = __float2half_rn(v0), h1 = __float2half_rn(v1);
    return (uint32_t)__half_as_ushort(h0) | ((uint32_t)__half_as_ushort(h1) << 16);
}

// ============================================================================
// Prep A: grid_feat -> fragment-major fp16 image (hi only)
// block = (rt 256, cg 8); cg covers channels [cg*32, cg*32+32) = one k-chunk
// ============================================================================
__global__ void vq_prepA(const float* __restrict__ gf) {
    __shared__ float sr[32 * 129];
    const int rt = blockIdx.x, cg = blockIdx.y, t = threadIdx.x;
    const int n0 = rt * MT, b = n0 >> 12, p0 = n0 & (SPATIAL - 1);
    const float* base = gf + (size_t)b * KDIM * SPATIAL + (size_t)(cg * 32) * SPATIAL + p0;

    for (int i = t; i < 32 * 128; i += 256) {
        const int c = i >> 7, r = i & 127;            // coalesced along spatial
        sr[c * 129 + r] = base[(size_t)c * SPATIAL + r];
    }
    __syncthreads();

    uint4* ob = (uint4*)g_Aimg + (size_t)rt * (NCH * A_CH_F4);
    #pragma unroll
    for (int q = 0; q < 2; q++) {
        const int tup = q * 256 + t;                  // 512 tuples
        const int ktl = tup >> 8, mt = (tup >> 5) & 7, l = tup & 31;
        const int m0 = mt * 16 + (l >> 2);
        const int k0 = ktl * 16 + (l & 3) * 2;
        const uint32_t h0 = pack2h(sr[k0 * 129 + m0],           sr[(k0 + 1) * 129 + m0]);
        const uint32_t h1 = pack2h(sr[k0 * 129 + m0 + 8],       sr[(k0 + 1) * 129 + m0 + 8]);
        const uint32_t h2 = pack2h(sr[(k0 + 8) * 129 + m0],     sr[(k0 + 9) * 129 + m0]);
        const uint32_t h3 = pack2h(sr[(k0 + 8) * 129 + m0 + 8], sr[(k0 + 9) * 129 + m0 + 8]);
        const int ktg = cg * 2 + ktl;
        ob[(ktg * 8 + mt) * 32 + l] = make_uint4(h0, h1, h2, h3);
    }
}

// ============================================================================
// Prep B: weight -> fragment-major fp16 image (hi only). block = (vt 16, cg 8)
// ============================================================================
__global__ void vq_prepB(const float* __restrict__ W) {
    __shared__ float sr2[32 * 257];
    const int vt = blockIdx.x, cg = blockIdx.y, t = threadIdx.x;
    const float* base = W + (size_t)(vt * NTT) * KDIM + cg * 32;

    for (int i = t; i < 256 * 32; i += 256) {
        const int n = i >> 5, c = i & 31;             // coalesced along channels
        sr2[c * 257 + n] = base[(size_t)n * KDIM + c];
    }
    __syncthreads();

    uint4* ob = (uint4*)g_Bimg + (size_t)vt * (NCH * B_CH_F4);
    #pragma unroll
    for (int q = 0; q < 4; q++) {
        const int tup = q * 256 + t;                  // 1024 tuples
        const int ktl = tup >> 9, ntp = (tup >> 5) & 15, l = tup & 31;
        const int nA = ntp * 16 + (l >> 2);
        const int k0 = ktl * 16 + (l & 3) * 2;
        const uint32_t h0 = pack2h(sr2[k0 * 257 + nA],           sr2[(k0 + 1) * 257 + nA]);
        const uint32_t h1 = pack2h(sr2[(k0 + 8) * 257 + nA],     sr2[(k0 + 9) * 257 + nA]);
        const uint32_t h2 = pack2h(sr2[k0 * 257 + nA + 8],       sr2[(k0 + 1) * 257 + nA + 8]);
        const uint32_t h3 = pack2h(sr2[(k0 + 8) * 257 + nA + 8], sr2[(k0 + 9) * 257 + nA + 8]);
        const int ktg = cg * 2 + ktl;
        ob[(ktg * 16 + ntp) * 32 + l] = make_uint4(h0, h1, h2, h3);
    }
}

// ---- W transpose + ||w||^2 (validated R1) ; resets flag counter ------------
__global__ void vq_transpose(const float* __restrict__ W) {
    __shared__ float tile[32][33];
    const int v0 = blockIdx.x * 32, c0 = blockIdx.y * 32;
    const int tx = threadIdx.x, ty = threadIdx.y;
    #pragma unroll
    for (int j = 0; j < 32; j += 8)
        tile[ty + j][tx] = W[(size_t)(v0 + ty + j) * KDIM + c0 + tx];
    __syncthreads();
    #pragma unroll
    for (int j = 0; j < 32; j += 8)
        g_Wt[(size_t)(c0 + ty + j) * VCODES + v0 + tx] = tile[tx][ty + j];
}

__global__ void vq_wnorm(const float* __restrict__ W) {
    if (blockIdx.x == 0 && threadIdx.x == 0) g_nflag = 0;
    const int v = blockIdx.x * 8 + (threadIdx.x >> 5);
    const int lane = threadIdx.x & 31;
    const float4* p = reinterpret_cast<const float4*>(W + (size_t)v * KDIM);
    float s = 0.f;
    #pragma unroll
    for (int i = 0; i < 2; i++) {
        float4 x = p[lane * 2 + i];
        s += x.x * x.x + x.y * x.y + x.z * x.z + x.w * x.w;
    }
    #pragma unroll
    for (int o = 16; o > 0; o >>= 1) s += __shfl_xor_sync(0xffffffffu, s, o);
    if (lane == 0) g_wnorm[v] = s;
}

// ============================================================================
// Main: 256 CTAs x 256 threads, 4-stage cp.async pipeline, warp tile 32x128
// Single hi*hi pass: 8 chunks per v-tile, 128 chunks total
// ============================================================================
__global__ void __launch_bounds__(256, 1)
vq_main(const float* __restrict__ gf, float* __restrict__ out) {
    extern __shared__ uint4 sm4[];
    const uint32_t smb = smem_u32(sm4);

    const int t  = threadIdx.x;
    const int l  = t & 31;
    const int w  = t >> 5;
    const int wr = w >> 1;       // 0..3 row group
    const int wc = w & 1;        // 0..1 col group
    const int rt = blockIdx.x;
    const int n0 = rt * MT;
    const int b  = n0 >> 12;
    const int p0 = n0 & (SPATIAL - 1);

    const uint4* Abase = (const uint4*)g_Aimg + (size_t)rt * (NCH * A_CH_F4);
    const uint4* Bbase = (const uint4*)g_Bimg;

    auto issue = [&](int ch, int slot) {
        const int vt = ch >> 3, kc = ch & 7;
        const uint4* As = Abase + kc * A_CH_F4;
        const uint4* Bs = Bbase + (size_t)vt * (NCH * B_CH_F4) + kc * B_CH_F4;
        const uint32_t sb = smb + slot * STAGE_F4 * 16;
        cp16(sb + t * 16,            As + t);
        cp16(sb + (t + 256) * 16,    As + t + 256);
        const uint32_t bb = sb + A_CH_F4 * 16;
        #pragma unroll
        for (int q = 0; q < 4; q++)
            cp16(bb + (t + 256 * q) * 16, Bs + t + 256 * q);
        CP_COMMIT();
    };

    float acc[2][16][4];
    float rmin[4], rmin2[4];
    int   ridx[4];
    #pragma unroll
    for (int q = 0; q < 4; q++) { rmin[q] = 3.4e38f; rmin2[q] = 3.4e38f; ridx[q] = 0; }

    issue(0, 0); issue(1, 1); issue(2, 2);

    for (int ch = 0; ch < TOTAL_CH; ch++) {
        if (ch + 3 < TOTAL_CH) {
            CP_WAIT(2);                 // groups <= ch complete
            __syncthreads();            // all warps done reading slot (ch+3)&3
            issue(ch + 3, (ch + 3) & 3);
        } else {
            CP_WAIT(0);
            __syncthreads();
        }

        const uint4* S = sm4 + (ch & 3) * STAGE_F4;
        const int vt = ch >> 3, cc = ch & 7;

        if (cc == 0) {
            #pragma unroll
            for (int i = 0; i < 2; i++)
                #pragma unroll
                for (int j = 0; j < 16; j++)
                    #pragma unroll
                    for (int e = 0; e < 4; e++) acc[i][j][e] = 0.f;
        }

        #pragma unroll
        for (int ktl = 0; ktl < 2; ktl++) {
            const uint4 a0 = S[(ktl * 8 + wr * 2 + 0) * 32 + l];
            const uint4 a1 = S[(ktl * 8 + wr * 2 + 1) * 32 + l];
            #pragma unroll
            for (int jp = 0; jp < 8; jp++) {
                const uint4 bb = S[A_CH_F4 + (ktl * 16 + wc * 8 + jp) * 32 + l];
                mma16816(acc[0][2 * jp],     a0, bb.x, bb.y);
                mma16816(acc[1][2 * jp],     a1, bb.x, bb.y);
                mma16816(acc[0][2 * jp + 1], a0, bb.z, bb.w);
                mma16816(acc[1][2 * jp + 1], a1, bb.z, bb.w);
            }
        }

        if (cc == CH_PER_VT - 1) {
            // epilogue: d = ||w||^2 - 2*score ; (min1,idx1) lex + min2
            #pragma unroll
            for (int i = 0; i < 2; i++) {
                #pragma unroll
                for (int jn = 0; jn < 16; jn++) {
                    const int cb = vt * NTT + (wc * 8 + (jn >> 1)) * 16
                                 + (jn & 1) * 8 + 2 * (l & 3);
                    const float w0 = __ldg(&g_wnorm[cb]);
                    const float w1 = __ldg(&g_wnorm[cb + 1]);
                    const float d0 = fmaf(-2.f, acc[i][jn][0], w0);
                    const float d1 = fmaf(-2.f, acc[i][jn][1], w1);
                    const float d2 = fmaf(-2.f, acc[i][jn][2], w0);
                    const float d3 = fmaf(-2.f, acc[i][jn][3], w1);
                    const int q0 = i * 2, q1 = i * 2 + 1;
                    if (d0 < rmin[q0]) { rmin2[q0] = rmin[q0]; rmin[q0] = d0; ridx[q0] = cb; }
                    else if (d0 < rmin2[q0]) rmin2[q0] = d0;
                    if (d1 < rmin[q0]) { rmin2[q0] = rmin[q0]; rmin[q0] = d1; ridx[q0] = cb + 1; }
                    else if (d1 < rmin2[q0]) rmin2[q0] = d1;
                    if (d2 < rmin[q1]) { rmin2[q1] = rmin[q1]; rmin[q1] = d2; ridx[q1] = cb; }
                    else if (d2 < rmin2[q1]) rmin2[q1] = d2;
                    if (d3 < rmin[q1]) { rmin2[q1] = rmin[q1]; rmin[q1] = d3; ridx[q1] = cb + 1; }
                    else if (d3 < rmin2[q1]) rmin2[q1] = d3;
                }
            }
        }
    }
    CP_WAIT(0);
    __syncthreads();

    // ---- cross-warp argmin merge (smem aliases pipeline stages) ------------
    float* dmin_s   = (float*)sm4;              // [128][8]
    int*   idx_s    = (int*)(dmin_s + 1024);    // [128][8]
    float* dmin2_s  = (float*)(idx_s + 1024);   // [128][8]
    int*   rowidx_s = (int*)(dmin2_s + 1024);   // [128]
    float* red      = (float*)(rowidx_s + 128); // [256]

    const int slot = wc * 4 + (l & 3);
    #pragma unroll
    for (int q = 0; q < 4; q++) {
        const int row = wr * 32 + (q >> 1) * 16 + (q & 1) * 8 + (l >> 2);
        dmin_s[row * 8 + slot]  = rmin[q];
        idx_s[row * 8 + slot]   = ridx[q];
        dmin2_s[row * 8 + slot] = rmin2[q];
    }
    __syncthreads();
    if (t < MT) {
        float bd = 3.4e38f, bd2 = 3.4e38f;
        int   bi = 0;
        #pragma unroll
        for (int s = 0; s < 8; s++) {
            const float d = dmin_s[t * 8 + s];
            const int   v = idx_s[t * 8 + s];
            if (d < bd || (d == bd && v < bi)) { bd2 = fminf(bd2, bd); bd = d; bi = v; }
            else bd2 = fminf(bd2, d);
            bd2 = fminf(bd2, dmin2_s[t * 8 + s]);
        }
        rowidx_s[t] = bi;
        out[2 * NQ + n0 + t] = (float)bi;       // enc_idx
        if (bd2 - bd < MARGIN) {                // ambiguous -> exact fallback
            const int pos = atomicAdd(&g_nflag, 1);
            if (pos < FLAGCAP) g_flagrows[pos] = n0 + t;
        }
    }
    __syncthreads();

    // ---- output phase: gather + straight-through + MSE partial -------------
    float diffsum = 0.f;
    const size_t obase = (size_t)b * KDIM * SPATIAL + p0;
    for (int i = t; i < MT * KDIM; i += 256) {
        const int c = i >> 7, r = i & 127;
        const int vi = rowidx_s[r];
        const float qv = g_Wt[(size_t)c * VCODES + vi];
        const float gv = gf[obase + (size_t)c * SPATIAL + r];
        const float st = (qv - gv) + gv;
        const float dd = gv - qv;
        diffsum += dd * dd;
        const size_t o = obase + (size_t)c * SPATIAL + r;
        out[o]      = qv;
        out[NQ + o] = st;
    }

    red[t] = diffsum;
    __syncthreads();
    #pragma unroll
    for (int o = 128; o > 0; o >>= 1) {
        if (t < o) red[t] += red[t + o];
        __syncthreads();
    }
    if (t == 0) g_partial[rt] = red[0];
}

// ============================================================================
// Exact fp32 fallback, batched 16 flagged rows per block (validated R6)
// ============================================================================
__global__ void vq_fix(const float* __restrict__ gf, float* __restrict__ out) {
    const int nf = min(g_nflag, FLAGCAP);
    __shared__ float fsh[16][KDIM];
    __shared__ float dsh[256];
    __shared__ int   ish[256];
    __shared__ int   rowid_s[16];
    const int t = threadIdx.x;

    for (int g = blockIdx.x; g * 16 < nf; g += gridDim.x) {
        const int ng = min(16, nf - g * 16);
        if (t < ng) rowid_s[t] = g_flagrows[g * 16 + t];
        __syncthreads();
        for (int rw = 0; rw < ng; rw++) {
            const int row = rowid_s[rw];
            const int b = row >> 12, p = row & (SPATIAL - 1);
            fsh[rw][t] = gf[(size_t)b * KDIM * SPATIAL + (size_t)t * SPATIAL + p];
        }
        __syncthreads();

        float bd[16]; int bi[16];
        #pragma unroll
        for (int rw = 0; rw < 16; rw++) { bd[rw] = 3.4e38f; bi[rw] = 0; }

        for (int v = t; v < VCODES; v += 256) {     // coalesced over g_Wt [c][v]
            float dot[16];
            #pragma unroll
            for (int rw = 0; rw < 16; rw++) dot[rw] = 0.f;
            for (int c = 0; c < KDIM; c++) {
                const float wv = g_Wt[(size_t)c * VCODES + v];
                #pragma unroll
                for (int rw = 0; rw < 16; rw++)
                    dot[rw] = fmaf(fsh[rw][c], wv, dot[rw]);
            }
            const float wn = g_wnorm[v];
            #pragma unroll
            for (int rw = 0; rw < 16; rw++) {
                const float d = fmaf(-2.f, dot[rw], wn);
                if (d < bd[rw]) { bd[rw] = d; bi[rw] = v; }  // ascending v
            }
        }

        for (int rw = 0; rw < ng; rw++) {
            dsh[t] = bd[rw]; ish[t] = bi[rw];
            __syncthreads();
            #pragma unroll
            for (int o = 128; o > 0; o >>= 1) {
                if (t < o) {
                    const float d2 = dsh[t + o]; const int i2 = ish[t + o];
                    if (d2 < dsh[t] || (d2 == dsh[t] && i2 < ish[t])) {
                        dsh[t] = d2; ish[t] = i2;
                    }
                }
                __syncthreads();
            }
            const int row = rowid_s[rw];
            const int newi = ish[0];
            const int oldi = (int)out[2 * NQ + row];
            __syncthreads();
            if (newi != oldi) {
                const int b = row >> 12, p = row & (SPATIAL - 1);
                const float gv = fsh[rw][t];
                const float qn = g_Wt[(size_t)t * VCODES + newi];
                const float qo = g_Wt[(size_t)t * VCODES + oldi];
                const size_t o = (size_t)b * KDIM * SPATIAL + (size_t)t * SPATIAL + p;
                out[o]      = qn;
                out[NQ + o] = (qn - gv) + gv;
                dsh[t] = (gv - qn) * (gv - qn) - (gv - qo) * (gv - qo);
                __syncthreads();
                #pragma unroll
                for (int o2 = 128; o2 > 0; o2 >>= 1) {
                    if (t < o2) dsh[t] += dsh[t + o2];
                    __syncthreads();
                }
                if (t == 0) {
                    atomicAdd(&g_partial[row / MT], dsh[0]);
                    out[2 * NQ + row] = (float)newi;
                }
            }
            __syncthreads();
        }
    }
}

__global__ void vq_final(float* __restrict__ out) {
    __shared__ float red[NRT];
    const int t = threadIdx.x;
    red[t] = g_partial[t];
    __syncthreads();
    #pragma unroll
    for (int o = 128; o > 0; o >>= 1) {
        if (t < o) red[t] += red[t + o];
        __syncthreads();
    }
    if (t == 0) out[2 * NQ + NROWS] = red[0] * (1.f / (float)NQ);
}

// ============================================================================
extern "C" void kernel_launch(void* const* d_in, const int* in_sizes, int n_in,
                              void* d_out, int out_size) {
    const float* grid_feat = (const float*)d_in[0];
    const float* weight    = (const float*)d_in[1];
    float* out = (float*)d_out;

    cudaFuncSetAttribute(vq_main,
                         cudaFuncAttributeMaxDynamicSharedMemorySize, SMEM_MAIN);

    vq_prepA<<<dim3(NRT, NCH), 256>>>(grid_feat);
    vq_prepB<<<dim3(NVT, NCH), 256>>>(weight);
    vq_transpose<<<dim3(VCODES / 32, KDIM / 32), dim3(32, 8)>>>(weight);
    vq_wnorm<<<VCODES / 8, 256>>>(weight);
    vq_main<<<NRT, 256, SMEM_MAIN>>>(grid_feat, out);
    vq_fix<<<128, 256>>>(grid_feat, out);
    vq_final<<<1, NRT>>>(out);
}